// round 14
// baseline (speedup 1.0000x reference)
#include <cuda_runtime.h>
#include <cuda_bf16.h>
#include <math.h>
#include <stdint.h>

#define T_STEPS 256
#define BATCH   128
#define DIM     128
#define HID     1024
#define G4      4096
#define NT      32        // weight tiles per layer (128 z-cols each)
#define KS      4         // split-K
#define NBLK    128
#define NTHR    1024      // 32 warps -> 8 per SMSP (deep latency hiding)
#define KT1     1152      // DIM + HID
#define KT2     2048      // 2*HID
#define KC      64        // k per smem chunk
#define SP      72        // smem row stride (bf16) — LDSM conflict-free
#define TILE_B  (128 * SP * 2)          // 18432 bytes per tile
#define STAGE_B (4 * TILE_B)            // Ah, Al, Bh, Bl = 73728
#define DSMEM_B (2 * STAGE_B)           // 2 stages = 147456

// ---------------- fp32 scratch -------------------------------------------------
__device__ __align__(16) float g_h2all[(size_t)T_STEPS * BATCH * HID];
__device__ __align__(16) float g_logits[(size_t)T_STEPS * BATCH * DIM];
__device__ __align__(16) float g_zpart[(size_t)KS * NT * BATCH * 128];
__device__ __align__(16) float g_c1[BATCH * HID];
__device__ __align__(16) float g_c2[BATCH * HID];
__device__ __align__(16) float g_lossbuf[T_STEPS * BATCH];
__device__ volatile unsigned g_bar_gen;
__device__ unsigned g_bar_cnt;

// ---------------- bf16 split operands ------------------------------------------
__device__ __align__(16) __nv_bfloat16 g_x_hi[(size_t)T_STEPS * BATCH * DIM];
__device__ __align__(16) __nv_bfloat16 g_x_lo[(size_t)T_STEPS * BATCH * DIM];
__device__ __align__(16) __nv_bfloat16 g_w1_hi[(size_t)G4 * KT1];
__device__ __align__(16) __nv_bfloat16 g_w1_lo[(size_t)G4 * KT1];
__device__ __align__(16) __nv_bfloat16 g_w2_hi[(size_t)G4 * KT2];
__device__ __align__(16) __nv_bfloat16 g_w2_lo[(size_t)G4 * KT2];
__device__ __align__(16) __nv_bfloat16 g_h1_hi[BATCH * HID];
__device__ __align__(16) __nv_bfloat16 g_h1_lo[BATCH * HID];
__device__ __align__(16) __nv_bfloat16 g_h2_hi[BATCH * HID];
__device__ __align__(16) __nv_bfloat16 g_h2_lo[BATCH * HID];

__device__ __forceinline__ float sigm(float x) { return 1.0f / (1.0f + __expf(-x)); }

__device__ __forceinline__ uint32_t smem_u32(const void* p) {
    uint32_t a;
    asm("{ .reg .u64 t; cvta.to.shared.u64 t, %1; cvt.u32.u64 %0, t; }" : "=r"(a) : "l"(p));
    return a;
}

// ---------------- mma.sync m16n8k16 bf16 ----------------------------------------
__device__ __forceinline__ void mma16816(float* c, const uint32_t* a,
                                         uint32_t b0, uint32_t b1) {
    asm("mma.sync.aligned.m16n8k16.row.col.f32.bf16.bf16.f32 "
        "{%0,%1,%2,%3}, {%4,%5,%6,%7}, {%8,%9}, {%0,%1,%2,%3};"
        : "+f"(c[0]), "+f"(c[1]), "+f"(c[2]), "+f"(c[3])
        : "r"(a[0]), "r"(a[1]), "r"(a[2]), "r"(a[3]), "r"(b0), "r"(b1));
}

__device__ __forceinline__ void ldsm4(uint32_t* r, uint32_t a) {
    asm volatile("ldmatrix.sync.aligned.m8n8.x4.shared.b16 {%0,%1,%2,%3}, [%4];"
                 : "=r"(r[0]), "=r"(r[1]), "=r"(r[2]), "=r"(r[3]) : "r"(a));
}

// ---------------- grid-wide barrier ---------------------------------------------
__device__ __forceinline__ void grid_barrier() {
    __syncthreads();
    __threadfence();
    if (threadIdx.x == 0) {
        unsigned gen = g_bar_gen;
        if (atomicAdd(&g_bar_cnt, 1u) == NBLK - 1) {
            g_bar_cnt = 0;
            __threadfence();
            g_bar_gen = gen + 1;
        } else {
            while (g_bar_gen == gen) { __nanosleep(32); }
        }
    }
    __syncthreads();
}

// ---------------- conversion prolog kernels -------------------------------------
__global__ __launch_bounds__(256) void conv_x_kernel(const float* __restrict__ x) {
    size_t i = (size_t)blockIdx.x * 256 + threadIdx.x;
    float v = x[i];
    __nv_bfloat16 h = __float2bfloat16(v);
    g_x_hi[i] = h;
    g_x_lo[i] = __float2bfloat16(v - __bfloat162float(h));
}

__global__ __launch_bounds__(256) void conv_w1_kernel(const float* __restrict__ W) {
    size_t i = (size_t)blockIdx.x * 256 + threadIdx.x;
    if (i >= (size_t)KT1 * G4) return;
    int np = (int)(i & (G4 - 1));
    int k  = (int)(i >> 12);
    int tile = np >> 7, r = np & 127;
    int col = (r >> 5) * HID + tile * 32 + (r & 31);
    float v = W[(size_t)k * G4 + col];
    __nv_bfloat16 h = __float2bfloat16(v);
    g_w1_hi[(size_t)np * KT1 + k] = h;
    g_w1_lo[(size_t)np * KT1 + k] = __float2bfloat16(v - __bfloat162float(h));
}

__global__ __launch_bounds__(256) void conv_w2_kernel(const float* __restrict__ W) {
    size_t i = (size_t)blockIdx.x * 256 + threadIdx.x;
    if (i >= (size_t)KT2 * G4) return;
    int np = (int)(i & (G4 - 1));
    int k  = (int)(i >> 12);
    int tile = np >> 7, r = np & 127;
    int col = (r >> 5) * HID + tile * 32 + (r & 31);
    float v = W[(size_t)k * G4 + col];
    __nv_bfloat16 h = __float2bfloat16(v);
    g_w2_hi[(size_t)np * KT2 + k] = h;
    g_w2_lo[(size_t)np * KT2 + k] = __float2bfloat16(v - __bfloat162float(h));
}

// ---------------- cp.async tile copy: 128 rows x 64 bf16 -> smem ----------------
// 1024 16B chunks; 1024 threads -> exactly 1 per thread.
__device__ __forceinline__ void cp_tile(uint32_t dst,
                                        const __nv_bfloat16* __restrict__ src,
                                        int lda, int koff) {
    int i = threadIdx.x;            // [0,1024)
    int row = i >> 3, c = i & 7;
    uint32_t d = dst + (uint32_t)(row * SP + c * 8) * 2;
    const void* s = src + (size_t)row * lda + koff + c * 8;
    asm volatile("cp.async.cg.shared.global [%0], [%1], 16;" :: "r"(d), "l"(s));
}

template <int LAYER>
__device__ __forceinline__ void load_chunk(uint32_t stg, int t, int kg) {
    constexpr int XD = (LAYER == 1) ? DIM : HID;
    const __nv_bfloat16 *Ah, *Al;
    int lda, koff;
    if (LAYER == 1) {
        if (kg < XD) { Ah = g_x_hi + (size_t)t * BATCH * DIM;
                       Al = g_x_lo + (size_t)t * BATCH * DIM; lda = DIM; koff = kg; }
        else         { Ah = g_h1_hi; Al = g_h1_lo; lda = HID; koff = kg - XD; }
    } else {
        if (kg < XD) { Ah = g_h1_hi; Al = g_h1_lo; lda = HID; koff = kg; }
        else         { Ah = g_h2_hi; Al = g_h2_lo; lda = HID; koff = kg - XD; }
    }
    cp_tile(stg,          Ah, lda, koff);
    cp_tile(stg + TILE_B, Al, lda, koff);
}

// ---------------- tensor GEMM phase (pipelined, ldmatrix, 32 warps) -------------
// Warp tile: 16 rows x 32 cols. w>>2 selects rowgroup (8), w&3 selects colgroup (4).
template <int LAYER>
__device__ void gemm_phase_mma(int t, int ks, int tile, uint32_t smbase,
                               const __nv_bfloat16* __restrict__ Bh,
                               const __nv_bfloat16* __restrict__ Bl)
{
    constexpr int KT  = (LAYER == 1) ? KT1 : KT2;
    constexpr int KSL = KT / KS;                 // 288 / 512
    constexpr int NCH = (KSL + KC - 1) / KC;     // 5 (last short) / 8
    constexpr int KLAST = KSL - (NCH - 1) * KC;  // 32 / 64
    int kbase = ks * KSL;
    int tid = threadIdx.x;
    int w = tid >> 5, lane = tid & 31;
    int mr = (w >> 2) * 16;                 // 8 rowgroups of 16
    int nb = (w & 3) * 32;                  // 4 colgroups of 32
    int r = lane >> 2, cq = (lane & 3) * 2;
    int j = lane >> 3, i5 = lane & 7;

    uint32_t offA = (uint32_t)(((j & 1) * 8 + i5) * SP + (j >> 1) * 8) * 2;
    uint32_t offB = (uint32_t)(((j >> 1) * 8 + i5) * SP + (j & 1) * 8) * 2;

    float acc[4][4];                        // [n8][quad]
#pragma unroll
    for (int n = 0; n < 4; n++)
#pragma unroll
        for (int q = 0; q < 4; q++) acc[n][q] = 0.f;

    {
        uint32_t stg = smbase;
        load_chunk<LAYER>(stg, t, kbase);
        cp_tile(stg + 2 * TILE_B, Bh, KT, kbase);
        cp_tile(stg + 3 * TILE_B, Bl, KT, kbase);
        asm volatile("cp.async.commit_group;" ::: "memory");
    }

    for (int c = 0; c < NCH; c++) {
        asm volatile("cp.async.wait_group 0;" ::: "memory");
        __syncthreads();

        if (c + 1 < NCH) {
            uint32_t stg = smbase + ((c + 1) & 1) * STAGE_B;
            int kg = kbase + (c + 1) * KC;
            load_chunk<LAYER>(stg, t, kg);
            cp_tile(stg + 2 * TILE_B, Bh, KT, kg);
            cp_tile(stg + 3 * TILE_B, Bl, KT, kg);
            asm volatile("cp.async.commit_group;" ::: "memory");
        }

        uint32_t stg = smbase + (c & 1) * STAGE_B;
        uint32_t uAh = stg, uAl = stg + TILE_B;
        uint32_t uBh = stg + 2 * TILE_B, uBl = stg + 3 * TILE_B;

        int kmax = (c == NCH - 1) ? KLAST : KC;
#pragma unroll
        for (int kb = 0; kb < KC; kb += 16) {
            if (kb >= kmax) break;
            uint32_t ah[4], al[4];
            ldsm4(ah, uAh + (uint32_t)(mr * SP + kb) * 2 + offA);
            ldsm4(al, uAl + (uint32_t)(mr * SP + kb) * 2 + offA);
#pragma unroll
            for (int p = 0; p < 2; p++) {
                int nbase = nb + p * 16;
                uint32_t bh[4], bl[4];
                ldsm4(bh, uBh + (uint32_t)(nbase * SP + kb) * 2 + offB);
                ldsm4(bl, uBl + (uint32_t)(nbase * SP + kb) * 2 + offB);
                // interleave across the two n8 accumulators
                mma16816(acc[p * 2],     ah, bh[0], bh[1]);
                mma16816(acc[p * 2 + 1], ah, bh[2], bh[3]);
                mma16816(acc[p * 2],     ah, bl[0], bl[1]);
                mma16816(acc[p * 2 + 1], ah, bl[2], bl[3]);
                mma16816(acc[p * 2],     al, bh[0], bh[1]);
                mma16816(acc[p * 2 + 1], al, bh[2], bh[3]);
            }
        }
        __syncthreads();
    }

    float* zp = g_zpart + (size_t)(ks * NT + tile) * (BATCH * 128);
#pragma unroll
    for (int nt = 0; nt < 4; nt++) {
        int row0 = mr + r;
        int col = nb + nt * 8 + cq;
        *(float2*)(zp + (size_t)row0 * 128 + col) =
            make_float2(acc[nt][0], acc[nt][1]);
        *(float2*)(zp + (size_t)(row0 + 8) * 128 + col) =
            make_float2(acc[nt][2], acc[nt][3]);
    }
}

// ---------------- gate phase ----------------------------------------------------
template <int LAYER>
__device__ void gate_phase(const float* __restrict__ bias, int t, int gid)
{
    float* cs = (LAYER == 1) ? g_c1 : g_c2;
    __nv_bfloat16* hh_ = (LAYER == 1) ? g_h1_hi : g_h2_hi;
    __nv_bfloat16* hl_ = (LAYER == 1) ? g_h1_lo : g_h2_lo;

    int idx = gid;                  // NBLK*NTHR == BATCH*HID: 1 elem/thread
    int b  = idx >> 10;
    int hg = idx & (HID - 1);
    int tile = hg >> 5;
    int hh = hg & 31;

    float zi = 0.f, zj = 0.f, zf = 0.f, zo = 0.f;
#pragma unroll
    for (int s = 0; s < KS; s++) {
        const float* z = g_zpart + ((size_t)s * NT + tile) * (BATCH * 128)
                       + (size_t)b * 128;
        zi += z[hh]; zj += z[32 + hh]; zf += z[64 + hh]; zo += z[96 + hh];
    }
    zi += bias[hg];
    zj += bias[HID + hg];
    zf += bias[2 * HID + hg];
    zo += bias[3 * HID + hg];

    float cp = cs[idx];
    float fg = sigm(zf + 1.0f);
    float ig = sigm(zi);
    float jg = tanhf(zj);
    float og = sigm(zo);
    float cn = cp * fg + ig * jg;
    float hn = tanhf(cn) * og;
    cs[idx] = cn;
    __nv_bfloat16 bh = __float2bfloat16(hn);
    hh_[idx] = bh;
    hl_[idx] = __float2bfloat16(hn - __bfloat162float(bh));
    if (LAYER == 2)
        g_h2all[(size_t)t * BATCH * HID + idx] = hn;
}

// ---------------- persistent recurrence kernel ----------------------------------
__global__ __launch_bounds__(NTHR, 1) void lstm_mma_kernel(
    const float* __restrict__ b1, const float* __restrict__ b2)
{
    extern __shared__ __align__(16) char dsm[];
    uint32_t smbase = smem_u32(dsm);

    int bid = blockIdx.x;
    int tile = bid & 31, ks = bid >> 5;
    int gid = bid * NTHR + threadIdx.x;

    const __nv_bfloat16* B1h = g_w1_hi + (size_t)tile * 128 * KT1;
    const __nv_bfloat16* B1l = g_w1_lo + (size_t)tile * 128 * KT1;
    const __nv_bfloat16* B2h = g_w2_hi + (size_t)tile * 128 * KT2;
    const __nv_bfloat16* B2l = g_w2_lo + (size_t)tile * 128 * KT2;

    __nv_bfloat16 z16 = __float2bfloat16(0.f);
    {
        int i = gid;                // 1 elem/thread
        g_c1[i] = 0.f; g_c2[i] = 0.f;
        g_h1_hi[i] = z16; g_h1_lo[i] = z16;
        g_h2_hi[i] = z16; g_h2_lo[i] = z16;
    }
    grid_barrier();

    for (int t = 0; t < T_STEPS; t++) {
        gemm_phase_mma<1>(t, ks, tile, smbase, B1h, B1l);
        grid_barrier();
        gate_phase<1>(b1, t, gid);
        grid_barrier();
        gemm_phase_mma<2>(t, ks, tile, smbase, B2h, B2l);
        grid_barrier();
        gate_phase<2>(b2, t, gid);
        grid_barrier();
    }
}

// ---------------- epilog --------------------------------------------------------
__global__ __launch_bounds__(256) void logits_kernel(
    const float* __restrict__ W, const float* __restrict__ bias)
{
    int mt = blockIdx.x;
    __shared__ __align__(16) float As[16][128];
    __shared__ __align__(16) float Bs[16][128];
    int tid = threadIdx.x;
    int tx = tid & 15, ty = tid >> 4;
    float acc[8][8];
#pragma unroll
    for (int i = 0; i < 8; i++)
#pragma unroll
        for (int j = 0; j < 8; j++) acc[i][j] = 0.f;

    const float* Ab = g_h2all + (size_t)mt * 128 * HID;

    for (int k0 = 0; k0 < HID; k0 += 16) {
#pragma unroll
        for (int r = 0; r < 2; r++) {
            int p = tid + r * 256;
            int m = p >> 2, kq = (p & 3) * 4;
            float4 v = *(const float4*)(Ab + (size_t)m * HID + k0 + kq);
            As[kq + 0][m] = v.x; As[kq + 1][m] = v.y;
            As[kq + 2][m] = v.z; As[kq + 3][m] = v.w;
        }
#pragma unroll
        for (int r = 0; r < 2; r++) {
            int p = tid + r * 256;
            int kk = p >> 5, c4 = (p & 31) * 4;
            float4 v = *(const float4*)(W + (size_t)(k0 + kk) * DIM + c4);
            *(float4*)&Bs[kk][c4] = v;
        }
        __syncthreads();
#pragma unroll
        for (int k = 0; k < 16; k++) {
            float4 a0 = *(const float4*)&As[k][ty * 4];
            float4 a1 = *(const float4*)&As[k][ty * 4 + 64];
            float4 b0 = *(const float4*)&Bs[k][tx * 4];
            float4 b1 = *(const float4*)&Bs[k][tx * 4 + 64];
            float av[8] = {a0.x, a0.y, a0.z, a0.w, a1.x, a1.y, a1.z, a1.w};
            float bv[8] = {b0.x, b0.y, b0.z, b0.w, b1.x, b1.y, b1.z, b1.w};
#pragma unroll
            for (int i = 0; i < 8; i++)
#pragma unroll
                for (int j = 0; j < 8; j++)
                    acc[i][j] = fmaf(av[i], bv[j], acc[i][j]);
        }
        __syncthreads();
    }

#pragma unroll
    for (int i = 0; i < 8; i++) {
        int m = (i < 4) ? (ty * 4 + i) : (64 + ty * 4 + i - 4);
        float* orow = g_logits + (size_t)(mt * 128 + m) * DIM;
        int c0 = tx * 4;
        float4 o0, o1;
        o0.x = acc[i][0] + bias[c0 + 0];
        o0.y = acc[i][1] + bias[c0 + 1];
        o0.z = acc[i][2] + bias[c0 + 2];
        o0.w = acc[i][3] + bias[c0 + 3];
        o1.x = acc[i][4] + bias[c0 + 64];
        o1.y = acc[i][5] + bias[c0 + 65];
        o1.z = acc[i][6] + bias[c0 + 66];
        o1.w = acc[i][7] + bias[c0 + 67];
        *(float4*)(orow + c0) = o0;
        *(float4*)(orow + c0 + 64) = o1;
    }
}

__global__ __launch_bounds__(256) void softmax_ce_kernel(
    const int* __restrict__ tgt, float* __restrict__ probs)
{
    int warp = (blockIdx.x * blockDim.x + threadIdx.x) >> 5;
    int lane = threadIdx.x & 31;
    if (warp >= T_STEPS * BATCH) return;
    const float* row = g_logits + (size_t)warp * 128;
    float v0 = row[lane], v1 = row[lane + 32], v2 = row[lane + 64], v3 = row[lane + 96];

    float m_mel = fmaxf(v0, lane < 16 ? v1 : -1e30f);
#pragma unroll
    for (int o = 16; o; o >>= 1) m_mel = fmaxf(m_mel, __shfl_xor_sync(~0u, m_mel, o));
    float e0 = __expf(v0 - m_mel);
    float e1m = (lane < 16) ? __expf(v1 - m_mel) : 0.f;
    float s_mel = e0 + e1m;
#pragma unroll
    for (int o = 16; o; o >>= 1) s_mel += __shfl_xor_sync(~0u, s_mel, o);

    float m_har = fmaxf(fmaxf(v2, v3), lane >= 16 ? v1 : -1e30f);
#pragma unroll
    for (int o = 16; o; o >>= 1) m_har = fmaxf(m_har, __shfl_xor_sync(~0u, m_har, o));
    float e1h = (lane >= 16) ? __expf(v1 - m_har) : 0.f;
    float e2 = __expf(v2 - m_har);
    float e3 = __expf(v3 - m_har);
    float s_har = e1h + e2 + e3;
#pragma unroll
    for (int o = 16; o; o >>= 1) s_har += __shfl_xor_sync(~0u, s_har, o);

    float inv_mel = 1.0f / s_mel;
    float inv_har = 1.0f / s_har;
    float* pr = probs + (size_t)warp * 128;
    pr[lane]      = e0 * inv_mel;
    pr[lane + 32] = (lane < 16) ? e1m * inv_mel : e1h * inv_har;
    pr[lane + 64] = e2 * inv_har;
    pr[lane + 96] = e3 * inv_har;

    if (lane == 0) {
        int t0 = tgt[warp * 2 + 0];
        int t1 = tgt[warp * 2 + 1];
        t0 = min(max(t0, 0), 47);
        t1 = min(max(t1, 0), 79);
        float l0 = row[t0];
        float l1 = row[48 + t1];
        float lse_mel = m_mel + logf(s_mel);
        float lse_har = m_har + logf(s_har);
        g_lossbuf[warp] = 0.5f * (lse_mel - l0) + 0.5f * (lse_har - l1);
    }
}

__global__ __launch_bounds__(256) void loss_reduce_kernel(float* __restrict__ out)
{
    __shared__ float sm[256];
    float s = 0.f;
    for (int i = threadIdx.x; i < T_STEPS * BATCH; i += 256) s += g_lossbuf[i];
    sm[threadIdx.x] = s;
    __syncthreads();
    for (int o = 128; o; o >>= 1) {
        if (threadIdx.x < o) sm[threadIdx.x] += sm[threadIdx.x + o];
        __syncthreads();
    }
    if (threadIdx.x == 0)
        out[0] = sm[0] / (float)(T_STEPS * BATCH);
}

// ---------------- launch --------------------------------------------------------
extern "C" void kernel_launch(void* const* d_in, const int* in_sizes, int n_in,
                              void* d_out, int out_size)
{
    const float* inSeq = (const float*)d_in[0];
    const int*   tgt   = (const int*)d_in[1];
    const float* W1    = (const float*)d_in[2];
    const float* b1    = (const float*)d_in[3];
    const float* W2    = (const float*)d_in[4];
    const float* b2    = (const float*)d_in[5];
    const float* outW  = (const float*)d_in[6];
    const float* outB  = (const float*)d_in[7];
    float* out = (float*)d_out;

    cudaFuncSetAttribute(lstm_mma_kernel,
                         cudaFuncAttributeMaxDynamicSharedMemorySize, DSMEM_B);

    conv_x_kernel<<<(T_STEPS * BATCH * DIM) / 256, 256>>>(inSeq);
    conv_w1_kernel<<<(int)(((size_t)KT1 * G4 + 255) / 256), 256>>>(W1);
    conv_w2_kernel<<<(int)(((size_t)KT2 * G4 + 255) / 256), 256>>>(W2);

    lstm_mma_kernel<<<NBLK, NTHR, DSMEM_B>>>(b1, b2);

    logits_kernel<<<(T_STEPS * BATCH) / 128, 256>>>(outW, outB);
    softmax_ce_kernel<<<(T_STEPS * BATCH * 32) / 256, 256>>>(tgt, out);
    loss_reduce_kernel<<<1, 256>>>(out + (out_size - 1));
}

// round 15
// speedup vs baseline: 1.0316x; 1.0316x over previous
#include <cuda_runtime.h>
#include <cuda_bf16.h>
#include <math.h>
#include <stdint.h>

#define T_STEPS 256
#define BATCH   128
#define DIM     128
#define HID     1024
#define G4      4096
#define NT      32        // weight tiles per layer (128 z-cols each)
#define KS      4         // split-K
#define NBLK    128
#define NTHR    512       // 16 warps -> 4 per SMSP
#define KT1     1152      // DIM + HID
#define KT2     2048      // 2*HID
#define KC      64        // k per smem chunk
#define SP      72        // smem row stride (bf16) — LDSM conflict-free
#define TILE_B  (128 * SP * 2)          // 18432 bytes per tile
#define STAGE_B (4 * TILE_B)            // Ah, Al, Bh, Bl = 73728
#define DSMEM_B (2 * STAGE_B)           // 2 stages = 147456

// ---------------- fp32 scratch -------------------------------------------------
__device__ __align__(16) float g_h2all[(size_t)T_STEPS * BATCH * HID];
__device__ __align__(16) float g_logits[(size_t)T_STEPS * BATCH * DIM];
__device__ __align__(16) float g_zpart[(size_t)KS * NT * BATCH * 128];
__device__ __align__(16) float g_c1[BATCH * HID];
__device__ __align__(16) float g_c2[BATCH * HID];
__device__ __align__(16) float g_lossbuf[T_STEPS * BATCH];
__device__ unsigned g_gcnt[2][NT];        // monotonic per-tile split-K counters
__device__ volatile unsigned g_bar_gen;
__device__ unsigned g_bar_cnt;

// ---------------- bf16 split operands ------------------------------------------
__device__ __align__(16) __nv_bfloat16 g_x_hi[(size_t)T_STEPS * BATCH * DIM];
__device__ __align__(16) __nv_bfloat16 g_x_lo[(size_t)T_STEPS * BATCH * DIM];
__device__ __align__(16) __nv_bfloat16 g_w1_hi[(size_t)G4 * KT1];
__device__ __align__(16) __nv_bfloat16 g_w1_lo[(size_t)G4 * KT1];
__device__ __align__(16) __nv_bfloat16 g_w2_hi[(size_t)G4 * KT2];
__device__ __align__(16) __nv_bfloat16 g_w2_lo[(size_t)G4 * KT2];
__device__ __align__(16) __nv_bfloat16 g_h1_hi[BATCH * HID];
__device__ __align__(16) __nv_bfloat16 g_h1_lo[BATCH * HID];
__device__ __align__(16) __nv_bfloat16 g_h2_hi[BATCH * HID];
__device__ __align__(16) __nv_bfloat16 g_h2_lo[BATCH * HID];

__device__ __forceinline__ float sigm(float x) { return 1.0f / (1.0f + __expf(-x)); }

__device__ __forceinline__ uint32_t smem_u32(const void* p) {
    uint32_t a;
    asm("{ .reg .u64 t; cvta.to.shared.u64 t, %1; cvt.u32.u64 %0, t; }" : "=r"(a) : "l"(p));
    return a;
}

// ---------------- mma.sync m16n8k16 bf16 ----------------------------------------
__device__ __forceinline__ void mma16816(float* c, const uint32_t* a,
                                         uint32_t b0, uint32_t b1) {
    asm("mma.sync.aligned.m16n8k16.row.col.f32.bf16.bf16.f32 "
        "{%0,%1,%2,%3}, {%4,%5,%6,%7}, {%8,%9}, {%0,%1,%2,%3};"
        : "+f"(c[0]), "+f"(c[1]), "+f"(c[2]), "+f"(c[3])
        : "r"(a[0]), "r"(a[1]), "r"(a[2]), "r"(a[3]), "r"(b0), "r"(b1));
}

__device__ __forceinline__ void ldsm4(uint32_t* r, uint32_t a) {
    asm volatile("ldmatrix.sync.aligned.m8n8.x4.shared.b16 {%0,%1,%2,%3}, [%4];"
                 : "=r"(r[0]), "=r"(r[1]), "=r"(r[2]), "=r"(r[3]) : "r"(a));
}

// ---------------- grid-wide barrier ---------------------------------------------
__device__ __forceinline__ void grid_barrier() {
    __syncthreads();
    __threadfence();
    if (threadIdx.x == 0) {
        unsigned gen = g_bar_gen;
        if (atomicAdd(&g_bar_cnt, 1u) == NBLK - 1) {
            g_bar_cnt = 0;
            __threadfence();
            g_bar_gen = gen + 1;
        } else {
            while (g_bar_gen == gen) { __nanosleep(32); }
        }
    }
    __syncthreads();
}

// ---------------- per-tile split-K rendezvous (4 blocks) -------------------------
// Monotonic counter: target KS*(t+1); reset once at kernel start.
template <int L>
__device__ __forceinline__ void tile_sync(int t, int tile) {
    __threadfence();                 // release: publish zpart stores
    __syncthreads();
    if (threadIdx.x == 0) {
        atomicAdd(&g_gcnt[L][tile], 1u);
        unsigned tgt = (unsigned)KS * (unsigned)(t + 1);
        while (*(volatile unsigned*)&g_gcnt[L][tile] < tgt) __nanosleep(32);
    }
    __syncthreads();
    __threadfence();                 // acquire: see peers' zpart (invalidate L1)
}

// ---------------- conversion prolog kernels -------------------------------------
__global__ __launch_bounds__(256) void conv_x_kernel(const float* __restrict__ x) {
    size_t i = (size_t)blockIdx.x * 256 + threadIdx.x;
    float v = x[i];
    __nv_bfloat16 h = __float2bfloat16(v);
    g_x_hi[i] = h;
    g_x_lo[i] = __float2bfloat16(v - __bfloat162float(h));
}

__global__ __launch_bounds__(256) void conv_w1_kernel(const float* __restrict__ W) {
    size_t i = (size_t)blockIdx.x * 256 + threadIdx.x;
    if (i >= (size_t)KT1 * G4) return;
    int np = (int)(i & (G4 - 1));
    int k  = (int)(i >> 12);
    int tile = np >> 7, r = np & 127;
    int col = (r >> 5) * HID + tile * 32 + (r & 31);
    float v = W[(size_t)k * G4 + col];
    __nv_bfloat16 h = __float2bfloat16(v);
    g_w1_hi[(size_t)np * KT1 + k] = h;
    g_w1_lo[(size_t)np * KT1 + k] = __float2bfloat16(v - __bfloat162float(h));
}

__global__ __launch_bounds__(256) void conv_w2_kernel(const float* __restrict__ W) {
    size_t i = (size_t)blockIdx.x * 256 + threadIdx.x;
    if (i >= (size_t)KT2 * G4) return;
    int np = (int)(i & (G4 - 1));
    int k  = (int)(i >> 12);
    int tile = np >> 7, r = np & 127;
    int col = (r >> 5) * HID + tile * 32 + (r & 31);
    float v = W[(size_t)k * G4 + col];
    __nv_bfloat16 h = __float2bfloat16(v);
    g_w2_hi[(size_t)np * KT2 + k] = h;
    g_w2_lo[(size_t)np * KT2 + k] = __float2bfloat16(v - __bfloat162float(h));
}

// ---------------- cp.async tile copy: 128 rows x 64 bf16 -> smem ----------------
// 1024 16B chunks; 512 threads -> 2 per thread.
__device__ __forceinline__ void cp_tile(uint32_t dst,
                                        const __nv_bfloat16* __restrict__ src,
                                        int lda, int koff) {
#pragma unroll
    for (int q = 0; q < 2; q++) {
        int i = threadIdx.x + q * 512;   // [0,1024)
        int row = i >> 3, c = i & 7;
        uint32_t d = dst + (uint32_t)(row * SP + c * 8) * 2;
        const void* s = src + (size_t)row * lda + koff + c * 8;
        asm volatile("cp.async.cg.shared.global [%0], [%1], 16;" :: "r"(d), "l"(s));
    }
}

template <int LAYER>
__device__ __forceinline__ void load_chunk(uint32_t stg, int t, int kg) {
    constexpr int XD = (LAYER == 1) ? DIM : HID;
    const __nv_bfloat16 *Ah, *Al;
    int lda, koff;
    if (LAYER == 1) {
        if (kg < XD) { Ah = g_x_hi + (size_t)t * BATCH * DIM;
                       Al = g_x_lo + (size_t)t * BATCH * DIM; lda = DIM; koff = kg; }
        else         { Ah = g_h1_hi; Al = g_h1_lo; lda = HID; koff = kg - XD; }
    } else {
        if (kg < XD) { Ah = g_h1_hi; Al = g_h1_lo; lda = HID; koff = kg; }
        else         { Ah = g_h2_hi; Al = g_h2_lo; lda = HID; koff = kg - XD; }
    }
    cp_tile(stg,          Ah, lda, koff);
    cp_tile(stg + TILE_B, Al, lda, koff);
}

// ---------------- tensor GEMM phase (pipelined, ldmatrix, 16 warps) -------------
template <int LAYER>
__device__ void gemm_phase_mma(int t, int ks, int tile, uint32_t smbase,
                               const __nv_bfloat16* __restrict__ Bh,
                               const __nv_bfloat16* __restrict__ Bl)
{
    constexpr int KT  = (LAYER == 1) ? KT1 : KT2;
    constexpr int KSL = KT / KS;                 // 288 / 512
    constexpr int NCH = (KSL + KC - 1) / KC;     // 5 (last short) / 8
    constexpr int KLAST = KSL - (NCH - 1) * KC;  // 32 / 64
    int kbase = ks * KSL;
    int tid = threadIdx.x;
    int w = tid >> 5, lane = tid & 31;
    int mr = (w >> 2) * 32;
    int nb = (w & 3) * 32;
    int r = lane >> 2, cq = (lane & 3) * 2;
    int j = lane >> 3, i5 = lane & 7;

    uint32_t offA = (uint32_t)(((j & 1) * 8 + i5) * SP + (j >> 1) * 8) * 2;
    uint32_t offB = (uint32_t)(((j >> 1) * 8 + i5) * SP + (j & 1) * 8) * 2;

    float acc[2][4][4];
#pragma unroll
    for (int a = 0; a < 2; a++)
#pragma unroll
        for (int n = 0; n < 4; n++)
#pragma unroll
            for (int q = 0; q < 4; q++) acc[a][n][q] = 0.f;

    {
        uint32_t stg = smbase;
        load_chunk<LAYER>(stg, t, kbase);
        cp_tile(stg + 2 * TILE_B, Bh, KT, kbase);
        cp_tile(stg + 3 * TILE_B, Bl, KT, kbase);
        asm volatile("cp.async.commit_group;" ::: "memory");
    }

    for (int c = 0; c < NCH; c++) {
        asm volatile("cp.async.wait_group 0;" ::: "memory");
        __syncthreads();

        if (c + 1 < NCH) {
            uint32_t stg = smbase + ((c + 1) & 1) * STAGE_B;
            int kg = kbase + (c + 1) * KC;
            load_chunk<LAYER>(stg, t, kg);
            cp_tile(stg + 2 * TILE_B, Bh, KT, kg);
            cp_tile(stg + 3 * TILE_B, Bl, KT, kg);
            asm volatile("cp.async.commit_group;" ::: "memory");
        }

        uint32_t stg = smbase + (c & 1) * STAGE_B;
        uint32_t uAh = stg, uAl = stg + TILE_B;
        uint32_t uBh = stg + 2 * TILE_B, uBl = stg + 3 * TILE_B;

        int kmax = (c == NCH - 1) ? KLAST : KC;
#pragma unroll
        for (int kb = 0; kb < KC; kb += 16) {
            if (kb >= kmax) break;
            uint32_t ah[2][4], al[2][4];
            ldsm4(ah[0], uAh + (uint32_t)(mr * SP + kb) * 2 + offA);
            ldsm4(ah[1], uAh + (uint32_t)((mr + 16) * SP + kb) * 2 + offA);
            ldsm4(al[0], uAl + (uint32_t)(mr * SP + kb) * 2 + offA);
            ldsm4(al[1], uAl + (uint32_t)((mr + 16) * SP + kb) * 2 + offA);
#pragma unroll
            for (int p = 0; p < 2; p++) {
                int nbase = nb + p * 16;
                uint32_t bh[4], bl[4];
                ldsm4(bh, uBh + (uint32_t)(nbase * SP + kb) * 2 + offB);
                ldsm4(bl, uBl + (uint32_t)(nbase * SP + kb) * 2 + offB);
#pragma unroll
                for (int mf = 0; mf < 2; mf++) {
                    mma16816(acc[mf][p * 2],     ah[mf], bh[0], bh[1]);
                    mma16816(acc[mf][p * 2 + 1], ah[mf], bh[2], bh[3]);
                    mma16816(acc[mf][p * 2],     ah[mf], bl[0], bl[1]);
                    mma16816(acc[mf][p * 2 + 1], ah[mf], bl[2], bl[3]);
                    mma16816(acc[mf][p * 2],     al[mf], bh[0], bh[1]);
                    mma16816(acc[mf][p * 2 + 1], al[mf], bh[2], bh[3]);
                }
            }
        }
        __syncthreads();
    }

    float* zp = g_zpart + (size_t)(ks * NT + tile) * (BATCH * 128);
#pragma unroll
    for (int mf = 0; mf < 2; mf++) {
#pragma unroll
        for (int nt = 0; nt < 4; nt++) {
            int row0 = mr + mf * 16 + r;
            int col = nb + nt * 8 + cq;
            *(float2*)(zp + (size_t)row0 * 128 + col) =
                make_float2(acc[mf][nt][0], acc[mf][nt][1]);
            *(float2*)(zp + (size_t)(row0 + 8) * 128 + col) =
                make_float2(acc[mf][nt][2], acc[mf][nt][3]);
        }
    }
}

// ---------------- gate phase: block (ks,tile) does its batch-quarter ------------
// 32 batch rows x 32 hidden units = 1024 elems, 2 per thread.
template <int LAYER>
__device__ void gate_phase(const float* __restrict__ bias, int t, int ks, int tile)
{
    float* cs = (LAYER == 1) ? g_c1 : g_c2;
    __nv_bfloat16* hh_ = (LAYER == 1) ? g_h1_hi : g_h2_hi;
    __nv_bfloat16* hl_ = (LAYER == 1) ? g_h1_lo : g_h2_lo;

#pragma unroll
    for (int e = 0; e < 2; e++) {
        int idx = threadIdx.x + e * NTHR;   // [0,1024)
        int bl = idx >> 5;
        int hh = idx & 31;
        int b = ks * 32 + bl;
        int hg = tile * 32 + hh;

        float zi = 0.f, zj = 0.f, zf = 0.f, zo = 0.f;
#pragma unroll
        for (int s = 0; s < KS; s++) {
            const float* z = g_zpart + ((size_t)s * NT + tile) * (BATCH * 128)
                           + (size_t)b * 128;
            zi += z[hh]; zj += z[32 + hh]; zf += z[64 + hh]; zo += z[96 + hh];
        }
        zi += bias[hg];
        zj += bias[HID + hg];
        zf += bias[2 * HID + hg];
        zo += bias[3 * HID + hg];

        int gidx = b * HID + hg;
        float cp = cs[gidx];
        float fg = sigm(zf + 1.0f);
        float ig = sigm(zi);
        float jg = tanhf(zj);
        float og = sigm(zo);
        float cn = cp * fg + ig * jg;
        float hn = tanhf(cn) * og;
        cs[gidx] = cn;
        __nv_bfloat16 bh16 = __float2bfloat16(hn);
        hh_[gidx] = bh16;
        hl_[gidx] = __float2bfloat16(hn - __bfloat162float(bh16));
        if (LAYER == 2)
            g_h2all[(size_t)t * BATCH * HID + gidx] = hn;
    }
}

// ---------------- persistent recurrence kernel ----------------------------------
__global__ __launch_bounds__(NTHR, 1) void lstm_mma_kernel(
    const float* __restrict__ b1, const float* __restrict__ b2)
{
    extern __shared__ __align__(16) char dsm[];
    uint32_t smbase = smem_u32(dsm);

    int bid = blockIdx.x;
    int tile = bid & 31, ks = bid >> 5;
    int gid = bid * NTHR + threadIdx.x;

    const __nv_bfloat16* B1h = g_w1_hi + (size_t)tile * 128 * KT1;
    const __nv_bfloat16* B1l = g_w1_lo + (size_t)tile * 128 * KT1;
    const __nv_bfloat16* B2h = g_w2_hi + (size_t)tile * 128 * KT2;
    const __nv_bfloat16* B2l = g_w2_lo + (size_t)tile * 128 * KT2;

    __nv_bfloat16 z16 = __float2bfloat16(0.f);
    for (int i = gid; i < BATCH * HID; i += NBLK * NTHR) {
        g_c1[i] = 0.f; g_c2[i] = 0.f;
        g_h1_hi[i] = z16; g_h1_lo[i] = z16;
        g_h2_hi[i] = z16; g_h2_lo[i] = z16;
    }
    if (ks == 0 && threadIdx.x == 0) {   // reset monotonic counters (graph replays)
        g_gcnt[0][tile] = 0;
        g_gcnt[1][tile] = 0;
    }
    grid_barrier();

    for (int t = 0; t < T_STEPS; t++) {
        gemm_phase_mma<1>(t, ks, tile, smbase, B1h, B1l);
        tile_sync<0>(t, tile);
        gate_phase<1>(b1, t, ks, tile);
        grid_barrier();
        gemm_phase_mma<2>(t, ks, tile, smbase, B2h, B2l);
        tile_sync<1>(t, tile);
        gate_phase<2>(b2, t, ks, tile);
        grid_barrier();
    }
}

// ---------------- epilog --------------------------------------------------------
__global__ __launch_bounds__(256) void logits_kernel(
    const float* __restrict__ W, const float* __restrict__ bias)
{
    int mt = blockIdx.x;
    __shared__ __align__(16) float As[16][128];
    __shared__ __align__(16) float Bs[16][128];
    int tid = threadIdx.x;
    int tx = tid & 15, ty = tid >> 4;
    float acc[8][8];
#pragma unroll
    for (int i = 0; i < 8; i++)
#pragma unroll
        for (int j = 0; j < 8; j++) acc[i][j] = 0.f;

    const float* Ab = g_h2all + (size_t)mt * 128 * HID;

    for (int k0 = 0; k0 < HID; k0 += 16) {
#pragma unroll
        for (int r = 0; r < 2; r++) {
            int p = tid + r * 256;
            int m = p >> 2, kq = (p & 3) * 4;
            float4 v = *(const float4*)(Ab + (size_t)m * HID + k0 + kq);
            As[kq + 0][m] = v.x; As[kq + 1][m] = v.y;
            As[kq + 2][m] = v.z; As[kq + 3][m] = v.w;
        }
#pragma unroll
        for (int r = 0; r < 2; r++) {
            int p = tid + r * 256;
            int kk = p >> 5, c4 = (p & 31) * 4;
            float4 v = *(const float4*)(W + (size_t)(k0 + kk) * DIM + c4);
            *(float4*)&Bs[kk][c4] = v;
        }
        __syncthreads();
#pragma unroll
        for (int k = 0; k < 16; k++) {
            float4 a0 = *(const float4*)&As[k][ty * 4];
            float4 a1 = *(const float4*)&As[k][ty * 4 + 64];
            float4 b0 = *(const float4*)&Bs[k][tx * 4];
            float4 b1 = *(const float4*)&Bs[k][tx * 4 + 64];
            float av[8] = {a0.x, a0.y, a0.z, a0.w, a1.x, a1.y, a1.z, a1.w};
            float bv[8] = {b0.x, b0.y, b0.z, b0.w, b1.x, b1.y, b1.z, b1.w};
#pragma unroll
            for (int i = 0; i < 8; i++)
#pragma unroll
                for (int j = 0; j < 8; j++)
                    acc[i][j] = fmaf(av[i], bv[j], acc[i][j]);
        }
        __syncthreads();
    }

#pragma unroll
    for (int i = 0; i < 8; i++) {
        int m = (i < 4) ? (ty * 4 + i) : (64 + ty * 4 + i - 4);
        float* orow = g_logits + (size_t)(mt * 128 + m) * DIM;
        int c0 = tx * 4;
        float4 o0, o1;
        o0.x = acc[i][0] + bias[c0 + 0];
        o0.y = acc[i][1] + bias[c0 + 1];
        o0.z = acc[i][2] + bias[c0 + 2];
        o0.w = acc[i][3] + bias[c0 + 3];
        o1.x = acc[i][4] + bias[c0 + 64];
        o1.y = acc[i][5] + bias[c0 + 65];
        o1.z = acc[i][6] + bias[c0 + 66];
        o1.w = acc[i][7] + bias[c0 + 67];
        *(float4*)(orow + c0) = o0;
        *(float4*)(orow + c0 + 64) = o1;
    }
}

__global__ __launch_bounds__(256) void softmax_ce_kernel(
    const int* __restrict__ tgt, float* __restrict__ probs)
{
    int warp = (blockIdx.x * blockDim.x + threadIdx.x) >> 5;
    int lane = threadIdx.x & 31;
    if (warp >= T_STEPS * BATCH) return;
    const float* row = g_logits + (size_t)warp * 128;
    float v0 = row[lane], v1 = row[lane + 32], v2 = row[lane + 64], v3 = row[lane + 96];

    float m_mel = fmaxf(v0, lane < 16 ? v1 : -1e30f);
#pragma unroll
    for (int o = 16; o; o >>= 1) m_mel = fmaxf(m_mel, __shfl_xor_sync(~0u, m_mel, o));
    float e0 = __expf(v0 - m_mel);
    float e1m = (lane < 16) ? __expf(v1 - m_mel) : 0.f;
    float s_mel = e0 + e1m;
#pragma unroll
    for (int o = 16; o; o >>= 1) s_mel += __shfl_xor_sync(~0u, s_mel, o);

    float m_har = fmaxf(fmaxf(v2, v3), lane >= 16 ? v1 : -1e30f);
#pragma unroll
    for (int o = 16; o; o >>= 1) m_har = fmaxf(m_har, __shfl_xor_sync(~0u, m_har, o));
    float e1h = (lane >= 16) ? __expf(v1 - m_har) : 0.f;
    float e2 = __expf(v2 - m_har);
    float e3 = __expf(v3 - m_har);
    float s_har = e1h + e2 + e3;
#pragma unroll
    for (int o = 16; o; o >>= 1) s_har += __shfl_xor_sync(~0u, s_har, o);

    float inv_mel = 1.0f / s_mel;
    float inv_har = 1.0f / s_har;
    float* pr = probs + (size_t)warp * 128;
    pr[lane]      = e0 * inv_mel;
    pr[lane + 32] = (lane < 16) ? e1m * inv_mel : e1h * inv_har;
    pr[lane + 64] = e2 * inv_har;
    pr[lane + 96] = e3 * inv_har;

    if (lane == 0) {
        int t0 = tgt[warp * 2 + 0];
        int t1 = tgt[warp * 2 + 1];
        t0 = min(max(t0, 0), 47);
        t1 = min(max(t1, 0), 79);
        float l0 = row[t0];
        float l1 = row[48 + t1];
        float lse_mel = m_mel + logf(s_mel);
        float lse_har = m_har + logf(s_har);
        g_lossbuf[warp] = 0.5f * (lse_mel - l0) + 0.5f * (lse_har - l1);
    }
}

__global__ __launch_bounds__(256) void loss_reduce_kernel(float* __restrict__ out)
{
    __shared__ float sm[256];
    float s = 0.f;
    for (int i = threadIdx.x; i < T_STEPS * BATCH; i += 256) s += g_lossbuf[i];
    sm[threadIdx.x] = s;
    __syncthreads();
    for (int o = 128; o; o >>= 1) {
        if (threadIdx.x < o) sm[threadIdx.x] += sm[threadIdx.x + o];
        __syncthreads();
    }
    if (threadIdx.x == 0)
        out[0] = sm[0] / (float)(T_STEPS * BATCH);
}

// ---------------- launch --------------------------------------------------------
extern "C" void kernel_launch(void* const* d_in, const int* in_sizes, int n_in,
                              void* d_out, int out_size)
{
    const float* inSeq = (const float*)d_in[0];
    const int*   tgt   = (const int*)d_in[1];
    const float* W1    = (const float*)d_in[2];
    const float* b1    = (const float*)d_in[3];
    const float* W2    = (const float*)d_in[4];
    const float* b2    = (const float*)d_in[5];
    const float* outW  = (const float*)d_in[6];
    const float* outB  = (const float*)d_in[7];
    float* out = (float*)d_out;

    cudaFuncSetAttribute(lstm_mma_kernel,
                         cudaFuncAttributeMaxDynamicSharedMemorySize, DSMEM_B);

    conv_x_kernel<<<(T_STEPS * BATCH * DIM) / 256, 256>>>(inSeq);
    conv_w1_kernel<<<(int)(((size_t)KT1 * G4 + 255) / 256), 256>>>(W1);
    conv_w2_kernel<<<(int)(((size_t)KT2 * G4 + 255) / 256), 256>>>(W2);

    lstm_mma_kernel<<<NBLK, NTHR, DSMEM_B>>>(b1, b2);

    logits_kernel<<<(T_STEPS * BATCH) / 128, 256>>>(outW, outB);
    softmax_ce_kernel<<<(T_STEPS * BATCH * 32) / 256, 256>>>(tgt, out);
    loss_reduce_kernel<<<1, 256>>>(out + (out_size - 1));
}

// round 16
// speedup vs baseline: 1.1431x; 1.1081x over previous
#include <cuda_runtime.h>
#include <cuda_bf16.h>
#include <math.h>
#include <stdint.h>

#define T_STEPS 256
#define BATCH   128
#define DIM     128
#define HID     1024
#define G4      4096
#define NT      32        // weight tiles per layer (128 z-cols each)
#define KS      4         // split-K
#define NBLK    128
#define NTHR    512       // 16 warps -> 4 per SMSP
#define KT1     1152      // DIM + HID
#define KT2     2048      // 2*HID
#define KC      64        // k per smem chunk
#define SP      72        // smem row stride (bf16) — LDSM conflict-free
#define TILE_B  (128 * SP * 2)          // 18432 bytes per tile
#define STAGE_B (4 * TILE_B)            // Ah, Al, Bh, Bl = 73728
#define DSMEM_B (2 * STAGE_B)           // 2 stages = 147456

// ---------------- fp32 scratch -------------------------------------------------
__device__ __align__(16) float g_h2all[(size_t)T_STEPS * BATCH * HID];
__device__ __align__(16) float g_logits[(size_t)T_STEPS * BATCH * DIM];
__device__ __align__(16) float g_zp1[(size_t)KS * NT * BATCH * 128];  // layer1 partials
__device__ __align__(16) float g_zp2[(size_t)KS * NT * BATCH * 128];  // layer2 partials
__device__ __align__(16) float g_c1[BATCH * HID];
__device__ __align__(16) float g_c2[BATCH * HID];
__device__ __align__(16) float g_lossbuf[T_STEPS * BATCH];
__device__ volatile unsigned g_bar_gen;
__device__ unsigned g_bar_cnt;

// ---------------- bf16 split operands ------------------------------------------
__device__ __align__(16) __nv_bfloat16 g_x_hi[(size_t)T_STEPS * BATCH * DIM];
__device__ __align__(16) __nv_bfloat16 g_x_lo[(size_t)T_STEPS * BATCH * DIM];
__device__ __align__(16) __nv_bfloat16 g_w1_hi[(size_t)G4 * KT1];
__device__ __align__(16) __nv_bfloat16 g_w1_lo[(size_t)G4 * KT1];
__device__ __align__(16) __nv_bfloat16 g_w2_hi[(size_t)G4 * KT2];
__device__ __align__(16) __nv_bfloat16 g_w2_lo[(size_t)G4 * KT2];
__device__ __align__(16) __nv_bfloat16 g_h1_hi[BATCH * HID];
__device__ __align__(16) __nv_bfloat16 g_h1_lo[BATCH * HID];
__device__ __align__(16) __nv_bfloat16 g_h2_hi[BATCH * HID];
__device__ __align__(16) __nv_bfloat16 g_h2_lo[BATCH * HID];

__device__ __forceinline__ float sigm(float x) { return 1.0f / (1.0f + __expf(-x)); }

__device__ __forceinline__ uint32_t smem_u32(const void* p) {
    uint32_t a;
    asm("{ .reg .u64 t; cvta.to.shared.u64 t, %1; cvt.u32.u64 %0, t; }" : "=r"(a) : "l"(p));
    return a;
}

// ---------------- mma.sync m16n8k16 bf16 ----------------------------------------
__device__ __forceinline__ void mma16816(float* c, const uint32_t* a,
                                         uint32_t b0, uint32_t b1) {
    asm("mma.sync.aligned.m16n8k16.row.col.f32.bf16.bf16.f32 "
        "{%0,%1,%2,%3}, {%4,%5,%6,%7}, {%8,%9}, {%0,%1,%2,%3};"
        : "+f"(c[0]), "+f"(c[1]), "+f"(c[2]), "+f"(c[3])
        : "r"(a[0]), "r"(a[1]), "r"(a[2]), "r"(a[3]), "r"(b0), "r"(b1));
}

__device__ __forceinline__ void ldsm4(uint32_t* r, uint32_t a) {
    asm volatile("ldmatrix.sync.aligned.m8n8.x4.shared.b16 {%0,%1,%2,%3}, [%4];"
                 : "=r"(r[0]), "=r"(r[1]), "=r"(r[2]), "=r"(r[3]) : "r"(a));
}

// ---------------- grid-wide barrier ---------------------------------------------
__device__ __forceinline__ void grid_barrier() {
    __syncthreads();
    __threadfence();
    if (threadIdx.x == 0) {
        unsigned gen = g_bar_gen;
        if (atomicAdd(&g_bar_cnt, 1u) == NBLK - 1) {
            g_bar_cnt = 0;
            __threadfence();
            g_bar_gen = gen + 1;
        } else {
            while (g_bar_gen == gen) { __nanosleep(32); }
        }
    }
    __syncthreads();
}

// ---------------- conversion prolog kernels -------------------------------------
__global__ __launch_bounds__(256) void conv_x_kernel(const float* __restrict__ x) {
    size_t i = (size_t)blockIdx.x * 256 + threadIdx.x;
    float v = x[i];
    __nv_bfloat16 h = __float2bfloat16(v);
    g_x_hi[i] = h;
    g_x_lo[i] = __float2bfloat16(v - __bfloat162float(h));
}

__global__ __launch_bounds__(256) void conv_w1_kernel(const float* __restrict__ W) {
    size_t i = (size_t)blockIdx.x * 256 + threadIdx.x;
    if (i >= (size_t)KT1 * G4) return;
    int np = (int)(i & (G4 - 1));
    int k  = (int)(i >> 12);
    int tile = np >> 7, r = np & 127;
    int col = (r >> 5) * HID + tile * 32 + (r & 31);
    float v = W[(size_t)k * G4 + col];
    __nv_bfloat16 h = __float2bfloat16(v);
    g_w1_hi[(size_t)np * KT1 + k] = h;
    g_w1_lo[(size_t)np * KT1 + k] = __float2bfloat16(v - __bfloat162float(h));
}

__global__ __launch_bounds__(256) void conv_w2_kernel(const float* __restrict__ W) {
    size_t i = (size_t)blockIdx.x * 256 + threadIdx.x;
    if (i >= (size_t)KT2 * G4) return;
    int np = (int)(i & (G4 - 1));
    int k  = (int)(i >> 12);
    int tile = np >> 7, r = np & 127;
    int col = (r >> 5) * HID + tile * 32 + (r & 31);
    float v = W[(size_t)k * G4 + col];
    __nv_bfloat16 h = __float2bfloat16(v);
    g_w2_hi[(size_t)np * KT2 + k] = h;
    g_w2_lo[(size_t)np * KT2 + k] = __float2bfloat16(v - __bfloat162float(h));
}

// ---------------- cp.async tile copy: 128 rows x 64 bf16 -> smem ----------------
__device__ __forceinline__ void cp_tile(uint32_t dst,
                                        const __nv_bfloat16* __restrict__ src,
                                        int lda, int koff) {
#pragma unroll
    for (int q = 0; q < 2; q++) {
        int i = threadIdx.x + q * 512;   // [0,1024)
        int row = i >> 3, c = i & 7;
        uint32_t d = dst + (uint32_t)(row * SP + c * 8) * 2;
        const void* s = src + (size_t)row * lda + koff + c * 8;
        asm volatile("cp.async.cg.shared.global [%0], [%1], 16;" :: "r"(d), "l"(s));
    }
}

template <int LAYER>
__device__ __forceinline__ void load_chunk(uint32_t stg, int t, int kg) {
    constexpr int XD = (LAYER == 1) ? DIM : HID;
    const __nv_bfloat16 *Ah, *Al;
    int lda, koff;
    if (LAYER == 1) {
        if (kg < XD) { Ah = g_x_hi + (size_t)t * BATCH * DIM;
                       Al = g_x_lo + (size_t)t * BATCH * DIM; lda = DIM; koff = kg; }
        else         { Ah = g_h1_hi; Al = g_h1_lo; lda = HID; koff = kg - XD; }
    } else {
        if (kg < XD) { Ah = g_h1_hi; Al = g_h1_lo; lda = HID; koff = kg; }
        else         { Ah = g_h2_hi; Al = g_h2_lo; lda = HID; koff = kg - XD; }
    }
    cp_tile(stg,          Ah, lda, koff);
    cp_tile(stg + TILE_B, Al, lda, koff);
}

// ---------------- tensor GEMM phase (pipelined, ldmatrix, 16 warps) -------------
template <int LAYER>
__device__ void gemm_phase_mma(int t, int ks, int tile, uint32_t smbase,
                               const __nv_bfloat16* __restrict__ Bh,
                               const __nv_bfloat16* __restrict__ Bl)
{
    constexpr int KT  = (LAYER == 1) ? KT1 : KT2;
    constexpr int KSL = KT / KS;                 // 288 / 512
    constexpr int NCH = (KSL + KC - 1) / KC;     // 5 (last short) / 8
    constexpr int KLAST = KSL - (NCH - 1) * KC;  // 32 / 64
    int kbase = ks * KSL;
    int tid = threadIdx.x;
    int w = tid >> 5, lane = tid & 31;
    int mr = (w >> 2) * 32;
    int nb = (w & 3) * 32;
    int r = lane >> 2, cq = (lane & 3) * 2;
    int j = lane >> 3, i5 = lane & 7;

    uint32_t offA = (uint32_t)(((j & 1) * 8 + i5) * SP + (j >> 1) * 8) * 2;
    uint32_t offB = (uint32_t)(((j >> 1) * 8 + i5) * SP + (j & 1) * 8) * 2;

    float acc[2][4][4];
#pragma unroll
    for (int a = 0; a < 2; a++)
#pragma unroll
        for (int n = 0; n < 4; n++)
#pragma unroll
            for (int q = 0; q < 4; q++) acc[a][n][q] = 0.f;

    {
        uint32_t stg = smbase;
        load_chunk<LAYER>(stg, t, kbase);
        cp_tile(stg + 2 * TILE_B, Bh, KT, kbase);
        cp_tile(stg + 3 * TILE_B, Bl, KT, kbase);
        asm volatile("cp.async.commit_group;" ::: "memory");
    }

    for (int c = 0; c < NCH; c++) {
        asm volatile("cp.async.wait_group 0;" ::: "memory");
        __syncthreads();

        if (c + 1 < NCH) {
            uint32_t stg = smbase + ((c + 1) & 1) * STAGE_B;
            int kg = kbase + (c + 1) * KC;
            load_chunk<LAYER>(stg, t, kg);
            cp_tile(stg + 2 * TILE_B, Bh, KT, kg);
            cp_tile(stg + 3 * TILE_B, Bl, KT, kg);
            asm volatile("cp.async.commit_group;" ::: "memory");
        }

        uint32_t stg = smbase + (c & 1) * STAGE_B;
        uint32_t uAh = stg, uAl = stg + TILE_B;
        uint32_t uBh = stg + 2 * TILE_B, uBl = stg + 3 * TILE_B;

        int kmax = (c == NCH - 1) ? KLAST : KC;
#pragma unroll
        for (int kb = 0; kb < KC; kb += 16) {
            if (kb >= kmax) break;
            uint32_t ah[2][4], al[2][4];
            ldsm4(ah[0], uAh + (uint32_t)(mr * SP + kb) * 2 + offA);
            ldsm4(ah[1], uAh + (uint32_t)((mr + 16) * SP + kb) * 2 + offA);
            ldsm4(al[0], uAl + (uint32_t)(mr * SP + kb) * 2 + offA);
            ldsm4(al[1], uAl + (uint32_t)((mr + 16) * SP + kb) * 2 + offA);
#pragma unroll
            for (int p = 0; p < 2; p++) {
                int nbase = nb + p * 16;
                uint32_t bh[4], bl[4];
                ldsm4(bh, uBh + (uint32_t)(nbase * SP + kb) * 2 + offB);
                ldsm4(bl, uBl + (uint32_t)(nbase * SP + kb) * 2 + offB);
#pragma unroll
                for (int mf = 0; mf < 2; mf++) {
                    mma16816(acc[mf][p * 2],     ah[mf], bh[0], bh[1]);
                    mma16816(acc[mf][p * 2 + 1], ah[mf], bh[2], bh[3]);
                    mma16816(acc[mf][p * 2],     ah[mf], bl[0], bl[1]);
                    mma16816(acc[mf][p * 2 + 1], ah[mf], bl[2], bl[3]);
                    mma16816(acc[mf][p * 2],     al[mf], bh[0], bh[1]);
                    mma16816(acc[mf][p * 2 + 1], al[mf], bh[2], bh[3]);
                }
            }
        }
        __syncthreads();
    }

    float* zp = ((LAYER == 1) ? g_zp1 : g_zp2)
              + (size_t)(ks * NT + tile) * (BATCH * 128);
#pragma unroll
    for (int mf = 0; mf < 2; mf++) {
#pragma unroll
        for (int nt = 0; nt < 4; nt++) {
            int row0 = mr + mf * 16 + r;
            int col = nb + nt * 8 + cq;
            *(float2*)(zp + (size_t)row0 * 128 + col) =
                make_float2(acc[mf][nt][0], acc[mf][nt][1]);
            *(float2*)(zp + (size_t)(row0 + 8) * 128 + col) =
                make_float2(acc[mf][nt][2], acc[mf][nt][3]);
        }
    }
}

// ---------------- gate phase: block (ks,tile) does its batch-quarter ------------
// 32 batch rows x 32 hidden units = 1024 elems, 2 per thread.
template <int LAYER>
__device__ void gate_phase(const float* __restrict__ bias, int t, int ks, int tile)
{
    const float* zbase = (LAYER == 1) ? g_zp1 : g_zp2;
    float* cs = (LAYER == 1) ? g_c1 : g_c2;
    __nv_bfloat16* hh_ = (LAYER == 1) ? g_h1_hi : g_h2_hi;
    __nv_bfloat16* hl_ = (LAYER == 1) ? g_h1_lo : g_h2_lo;

#pragma unroll
    for (int e = 0; e < 2; e++) {
        int idx = threadIdx.x + e * NTHR;   // [0,1024)
        int bl = idx >> 5;
        int hh = idx & 31;
        int b = ks * 32 + bl;
        int hg = tile * 32 + hh;

        float zi = 0.f, zj = 0.f, zf = 0.f, zo = 0.f;
#pragma unroll
        for (int s = 0; s < KS; s++) {
            const float* z = zbase + ((size_t)s * NT + tile) * (BATCH * 128)
                           + (size_t)b * 128;
            zi += z[hh]; zj += z[32 + hh]; zf += z[64 + hh]; zo += z[96 + hh];
        }
        zi += bias[hg];
        zj += bias[HID + hg];
        zf += bias[2 * HID + hg];
        zo += bias[3 * HID + hg];

        int gidx = b * HID + hg;
        float cp = cs[gidx];
        float fg = sigm(zf + 1.0f);
        float ig = sigm(zi);
        float jg = tanhf(zj);
        float og = sigm(zo);
        float cn = cp * fg + ig * jg;
        float hn = tanhf(cn) * og;
        cs[gidx] = cn;
        __nv_bfloat16 bh16 = __float2bfloat16(hn);
        hh_[gidx] = bh16;
        hl_[gidx] = __float2bfloat16(hn - __bfloat162float(bh16));
        if (LAYER == 2)
            g_h2all[(size_t)t * BATCH * HID + gidx] = hn;
    }
}

// ---------------- persistent recurrence kernel (cross-layer pipelined) ----------
// Phase overlap: gemm2(t) and gemm1(t+1) both depend only on state available
// after gate1(t) -> run back-to-back in ONE phase; gates merged likewise.
// 2 grid barriers per step instead of 4 sync points.
__global__ __launch_bounds__(NTHR, 1) void lstm_mma_kernel(
    const float* __restrict__ b1, const float* __restrict__ b2)
{
    extern __shared__ __align__(16) char dsm[];
    uint32_t smbase = smem_u32(dsm);

    int bid = blockIdx.x;
    int tile = bid & 31, ks = bid >> 5;
    int gid = bid * NTHR + threadIdx.x;

    const __nv_bfloat16* B1h = g_w1_hi + (size_t)tile * 128 * KT1;
    const __nv_bfloat16* B1l = g_w1_lo + (size_t)tile * 128 * KT1;
    const __nv_bfloat16* B2h = g_w2_hi + (size_t)tile * 128 * KT2;
    const __nv_bfloat16* B2l = g_w2_lo + (size_t)tile * 128 * KT2;

    __nv_bfloat16 z16 = __float2bfloat16(0.f);
    for (int i = gid; i < BATCH * HID; i += NBLK * NTHR) {
        g_c1[i] = 0.f; g_c2[i] = 0.f;
        g_h1_hi[i] = z16; g_h1_lo[i] = z16;
        g_h2_hi[i] = z16; g_h2_lo[i] = z16;
    }
    grid_barrier();

    // prime: layer1 step 0
    gemm_phase_mma<1>(0, ks, tile, smbase, B1h, B1l);
    grid_barrier();
    gate_phase<1>(b1, 0, ks, tile);
    grid_barrier();

    for (int t = 0; t < T_STEPS; t++) {
        gemm_phase_mma<2>(t, ks, tile, smbase, B2h, B2l);
        if (t + 1 < T_STEPS)
            gemm_phase_mma<1>(t + 1, ks, tile, smbase, B1h, B1l);
        grid_barrier();
        gate_phase<2>(b2, t, ks, tile);
        if (t + 1 < T_STEPS)
            gate_phase<1>(b1, t + 1, ks, tile);
        grid_barrier();
    }
}

// ---------------- epilog --------------------------------------------------------
__global__ __launch_bounds__(256) void logits_kernel(
    const float* __restrict__ W, const float* __restrict__ bias)
{
    int mt = blockIdx.x;
    __shared__ __align__(16) float As[16][128];
    __shared__ __align__(16) float Bs[16][128];
    int tid = threadIdx.x;
    int tx = tid & 15, ty = tid >> 4;
    float acc[8][8];
#pragma unroll
    for (int i = 0; i < 8; i++)
#pragma unroll
        for (int j = 0; j < 8; j++) acc[i][j] = 0.f;

    const float* Ab = g_h2all + (size_t)mt * 128 * HID;

    for (int k0 = 0; k0 < HID; k0 += 16) {
#pragma unroll
        for (int r = 0; r < 2; r++) {
            int p = tid + r * 256;
            int m = p >> 2, kq = (p & 3) * 4;
            float4 v = *(const float4*)(Ab + (size_t)m * HID + k0 + kq);
            As[kq + 0][m] = v.x; As[kq + 1][m] = v.y;
            As[kq + 2][m] = v.z; As[kq + 3][m] = v.w;
        }
#pragma unroll
        for (int r = 0; r < 2; r++) {
            int p = tid + r * 256;
            int kk = p >> 5, c4 = (p & 31) * 4;
            float4 v = *(const float4*)(W + (size_t)(k0 + kk) * DIM + c4);
            *(float4*)&Bs[kk][c4] = v;
        }
        __syncthreads();
#pragma unroll
        for (int k = 0; k < 16; k++) {
            float4 a0 = *(const float4*)&As[k][ty * 4];
            float4 a1 = *(const float4*)&As[k][ty * 4 + 64];
            float4 b0 = *(const float4*)&Bs[k][tx * 4];
            float4 b1 = *(const float4*)&Bs[k][tx * 4 + 64];
            float av[8] = {a0.x, a0.y, a0.z, a0.w, a1.x, a1.y, a1.z, a1.w};
            float bv[8] = {b0.x, b0.y, b0.z, b0.w, b1.x, b1.y, b1.z, b1.w};
#pragma unroll
            for (int i = 0; i < 8; i++)
#pragma unroll
                for (int j = 0; j < 8; j++)
                    acc[i][j] = fmaf(av[i], bv[j], acc[i][j]);
        }
        __syncthreads();
    }

#pragma unroll
    for (int i = 0; i < 8; i++) {
        int m = (i < 4) ? (ty * 4 + i) : (64 + ty * 4 + i - 4);
        float* orow = g_logits + (size_t)(mt * 128 + m) * DIM;
        int c0 = tx * 4;
        float4 o0, o1;
        o0.x = acc[i][0] + bias[c0 + 0];
        o0.y = acc[i][1] + bias[c0 + 1];
        o0.z = acc[i][2] + bias[c0 + 2];
        o0.w = acc[i][3] + bias[c0 + 3];
        o1.x = acc[i][4] + bias[c0 + 64];
        o1.y = acc[i][5] + bias[c0 + 65];
        o1.z = acc[i][6] + bias[c0 + 66];
        o1.w = acc[i][7] + bias[c0 + 67];
        *(float4*)(orow + c0) = o0;
        *(float4*)(orow + c0 + 64) = o1;
    }
}

__global__ __launch_bounds__(256) void softmax_ce_kernel(
    const int* __restrict__ tgt, float* __restrict__ probs)
{
    int warp = (blockIdx.x * blockDim.x + threadIdx.x) >> 5;
    int lane = threadIdx.x & 31;
    if (warp >= T_STEPS * BATCH) return;
    const float* row = g_logits + (size_t)warp * 128;
    float v0 = row[lane], v1 = row[lane + 32], v2 = row[lane + 64], v3 = row[lane + 96];

    float m_mel = fmaxf(v0, lane < 16 ? v1 : -1e30f);
#pragma unroll
    for (int o = 16; o; o >>= 1) m_mel = fmaxf(m_mel, __shfl_xor_sync(~0u, m_mel, o));
    float e0 = __expf(v0 - m_mel);
    float e1m = (lane < 16) ? __expf(v1 - m_mel) : 0.f;
    float s_mel = e0 + e1m;
#pragma unroll
    for (int o = 16; o; o >>= 1) s_mel += __shfl_xor_sync(~0u, s_mel, o);

    float m_har = fmaxf(fmaxf(v2, v3), lane >= 16 ? v1 : -1e30f);
#pragma unroll
    for (int o = 16; o; o >>= 1) m_har = fmaxf(m_har, __shfl_xor_sync(~0u, m_har, o));
    float e1h = (lane >= 16) ? __expf(v1 - m_har) : 0.f;
    float e2 = __expf(v2 - m_har);
    float e3 = __expf(v3 - m_har);
    float s_har = e1h + e2 + e3;
#pragma unroll
    for (int o = 16; o; o >>= 1) s_har += __shfl_xor_sync(~0u, s_har, o);

    float inv_mel = 1.0f / s_mel;
    float inv_har = 1.0f / s_har;
    float* pr = probs + (size_t)warp * 128;
    pr[lane]      = e0 * inv_mel;
    pr[lane + 32] = (lane < 16) ? e1m * inv_mel : e1h * inv_har;
    pr[lane + 64] = e2 * inv_har;
    pr[lane + 96] = e3 * inv_har;

    if (lane == 0) {
        int t0 = tgt[warp * 2 + 0];
        int t1 = tgt[warp * 2 + 1];
        t0 = min(max(t0, 0), 47);
        t1 = min(max(t1, 0), 79);
        float l0 = row[t0];
        float l1 = row[48 + t1];
        float lse_mel = m_mel + logf(s_mel);
        float lse_har = m_har + logf(s_har);
        g_lossbuf[warp] = 0.5f * (lse_mel - l0) + 0.5f * (lse_har - l1);
    }
}

__global__ __launch_bounds__(256) void loss_reduce_kernel(float* __restrict__ out)
{
    __shared__ float sm[256];
    float s = 0.f;
    for (int i = threadIdx.x; i < T_STEPS * BATCH; i += 256) s += g_lossbuf[i];
    sm[threadIdx.x] = s;
    __syncthreads();
    for (int o = 128; o; o >>= 1) {
        if (threadIdx.x < o) sm[threadIdx.x] += sm[threadIdx.x + o];
        __syncthreads();
    }
    if (threadIdx.x == 0)
        out[0] = sm[0] / (float)(T_STEPS * BATCH);
}

// ---------------- launch --------------------------------------------------------
extern "C" void kernel_launch(void* const* d_in, const int* in_sizes, int n_in,
                              void* d_out, int out_size)
{
    const float* inSeq = (const float*)d_in[0];
    const int*   tgt   = (const int*)d_in[1];
    const float* W1    = (const float*)d_in[2];
    const float* b1    = (const float*)d_in[3];
    const float* W2    = (const float*)d_in[4];
    const float* b2    = (const float*)d_in[5];
    const float* outW  = (const float*)d_in[6];
    const float* outB  = (const float*)d_in[7];
    float* out = (float*)d_out;

    cudaFuncSetAttribute(lstm_mma_kernel,
                         cudaFuncAttributeMaxDynamicSharedMemorySize, DSMEM_B);

    conv_x_kernel<<<(T_STEPS * BATCH * DIM) / 256, 256>>>(inSeq);
    conv_w1_kernel<<<(int)(((size_t)KT1 * G4 + 255) / 256), 256>>>(W1);
    conv_w2_kernel<<<(int)(((size_t)KT2 * G4 + 255) / 256), 256>>>(W2);

    lstm_mma_kernel<<<NBLK, NTHR, DSMEM_B>>>(b1, b2);

    logits_kernel<<<(T_STEPS * BATCH) / 128, 256>>>(outW, outB);
    softmax_ce_kernel<<<(T_STEPS * BATCH * 32) / 256, 256>>>(tgt, out);
    loss_reduce_kernel<<<1, 256>>>(out + (out_size - 1));
}